// round 8
// baseline (speedup 1.0000x reference)
#include <cuda_runtime.h>
#include <cuda_bf16.h>
#include <cuda_fp8.h>
#include <cstdint>

// Problem constants
#define N_ROWS 16384
#define D_IN   1024
#define D_OUT  512
#define N_EXP  8

// GEMM tiling
#define BM 128
#define BN 128
#define KC 32                           // main-K elems per chunk (64 B/row both streams)
#define NCHUNK (D_IN / KC)              // 32
#define NSTAGE 3
#define NTHREADS 512
#define MAX_TILES (N_ROWS / BM + N_EXP) // 136

// SMEM stage: 4 buffers (Ahi bf16, Ac fp8, Bhi bf16, Bc fp8), 128 rows x 80B
#define ROWB 80
#define BUFB (128 * ROWB)               // 10240
#define STG  (4 * BUFB)                 // 40960
#define SMEM_TOTAL (NSTAGE * STG)       // 122880

// ---------------- device scratch ------------------------------------------
__device__ int g_cnt[N_EXP];
__device__ int g_cur[N_EXP];
__device__ int g_off[N_EXP + 1];
__device__ int g_perm[N_ROWS];
__device__ int g_tile_e[MAX_TILES];
__device__ int g_tile_r[MAX_TILES];
__device__ __nv_bfloat16 g_xh[N_ROWS * D_IN];
__device__ uint8_t       g_xc[N_ROWS * 2 * D_IN];        // [xl*2^6 | xh*2^-4]
__device__ __nv_bfloat16 g_wh[N_EXP * D_OUT * D_IN];
__device__ uint8_t       g_wc[N_EXP * D_OUT * 2 * D_IN]; // [wh*2^4 | wl*2^14]

// ---------------- PTX helpers ----------------------------------------------
__device__ __forceinline__ uint32_t smem_u32(const void* p) {
    uint32_t a;
    asm("{ .reg .u64 t; cvta.to.shared.u64 t, %1; cvt.u32.u64 %0, t; }" : "=r"(a) : "l"(p));
    return a;
}
__device__ __forceinline__ void cp16(uint32_t dst, const void* src, bool ok) {
    int sz = ok ? 16 : 0;
    asm volatile("cp.async.cg.shared.global [%0], [%1], 16, %2;" :: "r"(dst), "l"(src), "r"(sz));
}
#define CP_COMMIT() asm volatile("cp.async.commit_group;" ::: "memory")
#define CP_WAIT(n)  asm volatile("cp.async.wait_group %0;" :: "n"(n) : "memory")

__device__ __forceinline__ void ldsm4(uint32_t* r, uint32_t a) {
    asm volatile("ldmatrix.sync.aligned.m8n8.x4.shared.b16 {%0,%1,%2,%3}, [%4];"
                 : "=r"(r[0]), "=r"(r[1]), "=r"(r[2]), "=r"(r[3]) : "r"(a));
}
__device__ __forceinline__ void mma_bf16(float* c, const uint32_t* a, uint32_t b0, uint32_t b1) {
    asm volatile("mma.sync.aligned.m16n8k16.row.col.f32.bf16.bf16.f32 "
                 "{%0,%1,%2,%3}, {%4,%5,%6,%7}, {%8,%9}, {%0,%1,%2,%3};"
                 : "+f"(c[0]), "+f"(c[1]), "+f"(c[2]), "+f"(c[3])
                 : "r"(a[0]), "r"(a[1]), "r"(a[2]), "r"(a[3]), "r"(b0), "r"(b1));
}
__device__ __forceinline__ void mma_fp8(float* c, const uint32_t* a, uint32_t b0, uint32_t b1) {
    asm volatile("mma.sync.aligned.m16n8k32.row.col.f32.e4m3.e4m3.f32 "
                 "{%0,%1,%2,%3}, {%4,%5,%6,%7}, {%8,%9}, {%0,%1,%2,%3};"
                 : "+f"(c[0]), "+f"(c[1]), "+f"(c[2]), "+f"(c[3])
                 : "r"(a[0]), "r"(a[1]), "r"(a[2]), "r"(a[3]), "r"(b0), "r"(b1));
}

// ---------------- bucketing -------------------------------------------------
__global__ void k_zero() {
    int t = threadIdx.x;
    if (t < N_EXP) { g_cnt[t] = 0; g_cur[t] = 0; }
}
__global__ void k_hist(const int* __restrict__ idx) {
    int i = blockIdx.x * blockDim.x + threadIdx.x;
    if (i < N_ROWS) atomicAdd(&g_cnt[idx[i]], 1);
}
__global__ void k_scan() {
    int off = 0, t = 0;
    for (int e = 0; e < N_EXP; ++e) {
        g_off[e] = off;
        int c = g_cnt[e];
        for (int r = 0; r < c; r += BM) { g_tile_e[t] = e; g_tile_r[t] = off + r; ++t; }
        off += c;
    }
    g_off[N_EXP] = off;
    for (; t < MAX_TILES; ++t) g_tile_e[t] = -1;
}
__global__ void k_scatter(const int* __restrict__ idx) {
    int i = blockIdx.x * blockDim.x + threadIdx.x;
    if (i < N_ROWS) {
        int e = idx[i];
        g_perm[g_off[e] + atomicAdd(&g_cur[e], 1)] = i;
    }
}

// ---------------- conversion ------------------------------------------------
__device__ __forceinline__ uint8_t f2e4m3(float v) {
    return (uint8_t)__nv_cvt_float_to_fp8(v, __NV_SATFINITE, __NV_E4M3);
}
__global__ void k_convert_x(const float* __restrict__ x) {
    int p = blockIdx.x;
    int src = g_perm[p];
    int t = threadIdx.x;                       // 256 threads x 4 elems
    float4 v = ((const float4*)(x + (size_t)src * D_IN))[t];
    float f[4] = {v.x, v.y, v.z, v.w};
    ushort4 h; uchar4 cl, ch;
    uint16_t* hp = (uint16_t*)&h; uint8_t* clp = (uint8_t*)&cl; uint8_t* chp = (uint8_t*)&ch;
    #pragma unroll
    for (int i = 0; i < 4; ++i) {
        __nv_bfloat16 hb = __float2bfloat16_rn(f[i]);
        float hf = __bfloat162float(hb);
        hp[i]  = __bfloat16_as_ushort(hb);
        clp[i] = f2e4m3((f[i] - hf) * 64.f);    // xl * 2^6
        chp[i] = f2e4m3(hf * 0.0625f);          // xh * 2^-4
    }
    ((ushort4*)(g_xh + (size_t)p * D_IN))[t] = h;
    ((uchar4*)(g_xc + (size_t)p * 2 * D_IN))[t] = cl;
    ((uchar4*)(g_xc + (size_t)p * 2 * D_IN + D_IN))[t] = ch;
}
__global__ void k_convert_w(const float* __restrict__ W) {
    int r = blockIdx.x;
    int t = threadIdx.x;
    float4 v = ((const float4*)(W + (size_t)r * D_IN))[t];
    float f[4] = {v.x, v.y, v.z, v.w};
    ushort4 h; uchar4 cl, ch;
    uint16_t* hp = (uint16_t*)&h; uint8_t* clp = (uint8_t*)&cl; uint8_t* chp = (uint8_t*)&ch;
    #pragma unroll
    for (int i = 0; i < 4; ++i) {
        __nv_bfloat16 hb = __float2bfloat16_rn(f[i]);
        float hf = __bfloat162float(hb);
        hp[i]  = __bfloat16_as_ushort(hb);
        clp[i] = f2e4m3(hf * 16.f);             // wh * 2^4
        chp[i] = f2e4m3((f[i] - hf) * 16384.f); // wl * 2^14
    }
    ((ushort4*)(g_wh + (size_t)r * D_IN))[t] = h;
    ((uchar4*)(g_wc + (size_t)r * 2 * D_IN))[t] = cl;
    ((uchar4*)(g_wc + (size_t)r * 2 * D_IN + D_IN))[t] = ch;
}

// ---------------- grouped GEMM: bf16 main + fp8 K-concat corrections --------
__device__ __forceinline__ void load_stage(uint32_t sb, int s, int row0, int e,
                                           int n0, int k0) {
    const int tid = threadIdx.x;
    const uint32_t st = sb + s * STG;
    #pragma unroll
    for (int it = 0; it < 4; ++it) {
        const int id  = tid + it * NTHREADS;  // 0..2047
        const int buf = id >> 9;              // 0:Ahi 1:Ac 2:Bhi 3:Bc
        const int rem = id & 511;
        const int r   = rem >> 2;             // row 0..127
        const int c   = rem & 3;              // 16B chunk 0..3
        const uint32_t dst = st + buf * BUFB + r * ROWB + c * 16;
        const void* src;
        bool ok = true;
        if (buf == 0) {
            const int gr = row0 + r;
            ok = gr < N_ROWS;
            src = g_xh + (size_t)(ok ? gr : 0) * D_IN + k0 + c * 8;
        } else if (buf == 1) {
            const int gr = row0 + r;
            ok = gr < N_ROWS;
            src = g_xc + (size_t)(ok ? gr : 0) * 2 * D_IN + 2 * k0 + c * 16;
        } else if (buf == 2) {
            src = g_wh + (size_t)(e * D_OUT + n0 + r) * D_IN + k0 + c * 8;
        } else {
            src = g_wc + (size_t)(e * D_OUT + n0 + r) * 2 * D_IN + 2 * k0 + c * 16;
        }
        cp16(dst, src, ok);
    }
}

__global__ void __launch_bounds__(NTHREADS, 1) k_gemm(const float* __restrict__ b,
                                                      float* __restrict__ y) {
    const int e = g_tile_e[blockIdx.x];
    if (e < 0) return;
    const int row0    = g_tile_r[blockIdx.x];
    const int row_end = g_off[e + 1];
    const int n0      = blockIdx.y * BN;

    extern __shared__ char smem[];
    const uint32_t sb = smem_u32(smem);

    const int tid    = threadIdx.x;
    const int lane   = tid & 31;
    const int warp   = tid >> 5;
    const int warp_m = warp >> 2;       // 0..3 (32 rows each)
    const int warp_n = warp & 3;        // 0..3 (32 cols each)

    // per warp: 32x32 tile = 2 m16-frags x 4 n8-frags
    float accA[2][4][4], accC[2][4][4];
    #pragma unroll
    for (int i = 0; i < 2; ++i)
        #pragma unroll
        for (int j = 0; j < 4; ++j)
            #pragma unroll
            for (int k = 0; k < 4; ++k) { accA[i][j][k] = 0.f; accC[i][j][k] = 0.f; }

    const uint32_t a_row  = warp_m * 32 + (lane & 15);
    const uint32_t a_koff = (lane >> 4) * 16;
    const uint32_t b_row  = warp_n * 32 + (lane & 7) + ((lane >> 4) & 1) * 8;
    const uint32_t b_koff = ((lane >> 3) & 1) * 16;

    load_stage(sb, 0, row0, e, n0, 0);
    CP_COMMIT();
    load_stage(sb, 1, row0, e, n0, KC);
    CP_COMMIT();

    int s = 0;
    for (int c = 0; c < NCHUNK; ++c) {
        CP_WAIT(1);
        __syncthreads();
        if (c + 2 < NCHUNK) load_stage(sb, (s + 2) % NSTAGE, row0, e, n0, (c + 2) * KC);
        CP_COMMIT();

        const uint32_t st = sb + s * STG;
        #pragma unroll
        for (int ks = 0; ks < 2; ++ks) {
            const uint32_t kb = ks * 32;
            uint32_t ah[2][4], ac[2][4], bh[2][4], bc[2][4];
            #pragma unroll
            for (int mt = 0; mt < 2; ++mt) {
                const uint32_t ad = st + (a_row + mt * 16) * ROWB + kb + a_koff;
                ldsm4(ah[mt], ad);               // bf16 hi (k16 span)
                ldsm4(ac[mt], ad + BUFB);        // fp8 concat (k32 span, same bytes)
            }
            #pragma unroll
            for (int nt2 = 0; nt2 < 2; ++nt2) {
                const uint32_t bd = st + 2 * BUFB + (b_row + nt2 * 16) * ROWB + kb + b_koff;
                ldsm4(bh[nt2], bd);
                ldsm4(bc[nt2], bd + BUFB);
            }
            #pragma unroll
            for (int mt = 0; mt < 2; ++mt)
                #pragma unroll
                for (int nt = 0; nt < 4; ++nt) {
                    const uint32_t* bhp = &bh[nt >> 1][(nt & 1) * 2];
                    const uint32_t* bcp = &bc[nt >> 1][(nt & 1) * 2];
                    mma_bf16(accA[mt][nt], ah[mt], bhp[0], bhp[1]);
                    mma_fp8 (accC[mt][nt], ac[mt], bcp[0], bcp[1]);
                }
        }
        s = (s + 1) % NSTAGE;
    }

    // epilogue: y = accA + accC*2^-10 + bias, scattered via perm
    const float cscale = 1.f / 1024.f;
    const int ncol = n0 + warp_n * 32 + (lane & 3) * 2;
    float2 bias[4];
    #pragma unroll
    for (int nt = 0; nt < 4; ++nt)
        bias[nt] = *(const float2*)(b + (size_t)e * D_OUT + ncol + nt * 8);

    #pragma unroll
    for (int mt = 0; mt < 2; ++mt)
        #pragma unroll
        for (int half = 0; half < 2; ++half) {
            const int sr = row0 + warp_m * 32 + mt * 16 + (lane >> 2) + half * 8;
            if (sr < row_end) {
                const int g = g_perm[sr];
                float* yp = y + (size_t)g * D_OUT + ncol;
                #pragma unroll
                for (int nt = 0; nt < 4; ++nt) {
                    float2 v;
                    v.x = accA[mt][nt][half * 2 + 0] + accC[mt][nt][half * 2 + 0] * cscale + bias[nt].x;
                    v.y = accA[mt][nt][half * 2 + 1] + accC[mt][nt][half * 2 + 1] * cscale + bias[nt].y;
                    *(float2*)(yp + nt * 8) = v;
                }
            }
        }
}

// ---------------- entry -----------------------------------------------------
extern "C" void kernel_launch(void* const* d_in, const int* in_sizes, int n_in,
                              void* d_out, int out_size) {
    const float* x   = (const float*)d_in[0];
    const int*   idx = (const int*)  d_in[1];
    const float* W   = (const float*)d_in[2];
    const float* b   = (const float*)d_in[3];
    float*       y   = (float*)d_out;

    cudaFuncSetAttribute(k_gemm, cudaFuncAttributeMaxDynamicSharedMemorySize, SMEM_TOTAL);

    k_zero<<<1, 32>>>();
    k_hist<<<(N_ROWS + 255) / 256, 256>>>(idx);
    k_scan<<<1, 1>>>();
    k_scatter<<<(N_ROWS + 255) / 256, 256>>>(idx);
    k_convert_x<<<N_ROWS, 256>>>(x);
    k_convert_w<<<N_EXP * D_OUT, 256>>>(W);

    dim3 grid(MAX_TILES, D_OUT / BN);
    k_gemm<<<grid, NTHREADS, SMEM_TOTAL>>>(b, y);
}

// round 10
// speedup vs baseline: 1.5238x; 1.5238x over previous
#include <cuda_runtime.h>
#include <cuda_bf16.h>
#include <cstdint>

// Problem constants
#define N_ROWS 16384
#define D_IN   1024
#define D_OUT  512
#define N_EXP  8

// GEMM tiling
#define BM 128
#define BN 128
#define KC 32                           // K elems per chunk = one k32 int8 MMA step
#define NCHUNK (D_IN / KC)              // 32
#define NSTAGE 4
#define NTHREADS 512
#define MAX_TILES (N_ROWS / BM + N_EXP) // 136

// SMEM stage: 4 buffers (X0, X1, W0, W1), each 128 rows x 32B data in 48B slots
#define ROWB 48
#define BUFB (128 * ROWB)               // 6144
#define STG  (4 * BUFB)                 // 24576
#define SMEM_TOTAL (NSTAGE * STG)       // 98304

// ---------------- device scratch ------------------------------------------
__device__ int g_cnt[N_EXP];
__device__ int g_cur[N_EXP];
__device__ int g_off[N_EXP + 1];
__device__ int g_perm[N_ROWS];
__device__ int g_tile_e[MAX_TILES];
__device__ int g_tile_r[MAX_TILES];
__device__ uint8_t g_x0[N_ROWS * D_IN];
__device__ uint8_t g_x1[N_ROWS * D_IN];
__device__ uint8_t g_w0[N_EXP * D_OUT * D_IN];
__device__ uint8_t g_w1[N_EXP * D_OUT * D_IN];
__device__ float   g_invqx[N_ROWS];
__device__ float   g_invqw[N_EXP * D_OUT];

// ---------------- PTX helpers ----------------------------------------------
__device__ __forceinline__ uint32_t smem_u32(const void* p) {
    uint32_t a;
    asm("{ .reg .u64 t; cvta.to.shared.u64 t, %1; cvt.u32.u64 %0, t; }" : "=r"(a) : "l"(p));
    return a;
}
__device__ __forceinline__ void cp16(uint32_t dst, const void* src, bool ok) {
    int sz = ok ? 16 : 0;
    asm volatile("cp.async.cg.shared.global [%0], [%1], 16, %2;" :: "r"(dst), "l"(src), "r"(sz));
}
#define CP_COMMIT() asm volatile("cp.async.commit_group;" ::: "memory")
#define CP_WAIT(n)  asm volatile("cp.async.wait_group %0;" :: "n"(n) : "memory")

__device__ __forceinline__ void ldsm4(uint32_t* r, uint32_t a) {
    asm volatile("ldmatrix.sync.aligned.m8n8.x4.shared.b16 {%0,%1,%2,%3}, [%4];"
                 : "=r"(r[0]), "=r"(r[1]), "=r"(r[2]), "=r"(r[3]) : "r"(a));
}
__device__ __forceinline__ void mma_s8(int* c, const uint32_t* a, uint32_t b0, uint32_t b1) {
    asm volatile("mma.sync.aligned.m16n8k32.row.col.s32.s8.s8.s32 "
                 "{%0,%1,%2,%3}, {%4,%5,%6,%7}, {%8,%9}, {%0,%1,%2,%3};"
                 : "+r"(c[0]), "+r"(c[1]), "+r"(c[2]), "+r"(c[3])
                 : "r"(a[0]), "r"(a[1]), "r"(a[2]), "r"(a[3]), "r"(b0), "r"(b1));
}

// ---------------- bucketing -------------------------------------------------
__global__ void k_zero() {
    int t = threadIdx.x;
    if (t < N_EXP) { g_cnt[t] = 0; g_cur[t] = 0; }
}
__global__ void k_hist(const int* __restrict__ idx) {
    int i = blockIdx.x * blockDim.x + threadIdx.x;
    if (i < N_ROWS) atomicAdd(&g_cnt[idx[i]], 1);
}
__global__ void k_scan() {
    int off = 0, t = 0;
    for (int e = 0; e < N_EXP; ++e) {
        g_off[e] = off;
        int c = g_cnt[e];
        for (int r = 0; r < c; r += BM) { g_tile_e[t] = e; g_tile_r[t] = off + r; ++t; }
        off += c;
    }
    g_off[N_EXP] = off;
    for (; t < MAX_TILES; ++t) g_tile_e[t] = -1;
}
__global__ void k_scatter(const int* __restrict__ idx) {
    int i = blockIdx.x * blockDim.x + threadIdx.x;
    if (i < N_ROWS) {
        int e = idx[i];
        g_perm[g_off[e] + atomicAdd(&g_cur[e], 1)] = i;
    }
}

// ---------------- int8 two-stream quantization ------------------------------
// row -> X0 = rint(x*q), X1 = rint((x*q - X0)*128), q = 127/rowmax; invq = rowmax/127
__device__ __forceinline__ void quant_row(const float* __restrict__ srcrow,
                                          uint8_t* __restrict__ d0,
                                          uint8_t* __restrict__ d1,
                                          float* __restrict__ invq_out) {
    __shared__ float red[8];
    const int t = threadIdx.x;                 // 256 threads x 4 floats
    float4 v = ((const float4*)srcrow)[t];
    float m = fmaxf(fmaxf(fabsf(v.x), fabsf(v.y)), fmaxf(fabsf(v.z), fabsf(v.w)));
    #pragma unroll
    for (int o = 16; o > 0; o >>= 1) m = fmaxf(m, __shfl_xor_sync(0xffffffffu, m, o));
    if ((t & 31) == 0) red[t >> 5] = m;
    __syncthreads();
    if (t < 32) {
        float mm = (t < 8) ? red[t] : 0.f;
        #pragma unroll
        for (int o = 4; o > 0; o >>= 1) mm = fmaxf(mm, __shfl_xor_sync(0xffffffffu, mm, o));
        if (t == 0) red[0] = fmaxf(mm, 1e-30f);
    }
    __syncthreads();
    const float maxv = red[0];
    const float q = 127.f / maxv;
    uchar4 c0, c1;
    uint8_t* p0 = (uint8_t*)&c0; uint8_t* p1 = (uint8_t*)&c1;
    float f[4] = {v.x, v.y, v.z, v.w};
    #pragma unroll
    for (int i = 0; i < 4; ++i) {
        float fq = f[i] * q;
        float x0 = rintf(fq);
        x0 = fminf(127.f, fmaxf(-127.f, x0));
        float x1 = rintf((fq - x0) * 128.f);
        x1 = fminf(127.f, fmaxf(-127.f, x1));
        p0[i] = (uint8_t)(int8_t)(int)x0;
        p1[i] = (uint8_t)(int8_t)(int)x1;
    }
    ((uchar4*)d0)[t] = c0;
    ((uchar4*)d1)[t] = c1;
    if (t == 0) *invq_out = maxv * (1.f / 127.f);
}

__global__ void k_convert_x(const float* __restrict__ x) {
    int p = blockIdx.x;                  // permuted row
    int src = g_perm[p];
    quant_row(x + (size_t)src * D_IN,
              g_x0 + (size_t)p * D_IN, g_x1 + (size_t)p * D_IN, &g_invqx[p]);
}
__global__ void k_convert_w(const float* __restrict__ W) {
    int r = blockIdx.x;                  // 0..E*D_OUT-1
    quant_row(W + (size_t)r * D_IN,
              g_w0 + (size_t)r * D_IN, g_w1 + (size_t)r * D_IN, &g_invqw[r]);
}

// ---------------- grouped int8 GEMM -----------------------------------------
__device__ __forceinline__ void load_stage(uint32_t sb, int s, int row0, int e,
                                           int n0, int k0) {
    const int tid = threadIdx.x;
    const uint32_t st = sb + s * STG;
    #pragma unroll
    for (int it = 0; it < 2; ++it) {
        const int id  = tid + it * NTHREADS;  // 0..1023
        const int buf = id >> 8;              // 0:X0 1:X1 2:W0 3:W1
        const int rem = id & 255;
        const int r   = rem >> 1;             // row 0..127
        const int c   = rem & 1;              // 16B chunk 0..1
        const uint32_t dst = st + buf * BUFB + r * ROWB + c * 16;
        const void* src;
        bool ok = true;
        if (buf < 2) {
            const int gr = row0 + r;
            ok = gr < N_ROWS;
            src = (buf == 0 ? g_x0 : g_x1) + (size_t)(ok ? gr : 0) * D_IN + k0 + c * 16;
        } else {
            src = (buf == 2 ? g_w0 : g_w1)
                + (size_t)(e * D_OUT + n0 + r) * D_IN + k0 + c * 16;
        }
        cp16(dst, src, ok);
    }
}

__global__ void __launch_bounds__(NTHREADS, 1) k_gemm(const float* __restrict__ b,
                                                      float* __restrict__ y) {
    const int e = g_tile_e[blockIdx.x];
    if (e < 0) return;
    const int row0    = g_tile_r[blockIdx.x];
    const int row_end = g_off[e + 1];
    const int n0      = blockIdx.y * BN;

    extern __shared__ char smem[];
    const uint32_t sb = smem_u32(smem);

    const int tid    = threadIdx.x;
    const int lane   = tid & 31;
    const int warp   = tid >> 5;
    const int warp_m = warp >> 2;       // 0..3 (32 rows each)
    const int warp_n = warp & 3;        // 0..3 (32 cols each)

    int accA[2][4][4], accC[2][4][4];
    #pragma unroll
    for (int i = 0; i < 2; ++i)
        #pragma unroll
        for (int j = 0; j < 4; ++j)
            #pragma unroll
            for (int k = 0; k < 4; ++k) { accA[i][j][k] = 0; accC[i][j][k] = 0; }

    const uint32_t a_row  = warp_m * 32 + (lane & 15);
    const uint32_t a_koff = (lane >> 4) * 16;
    const uint32_t b_row  = warp_n * 32 + (lane & 7) + ((lane >> 4) & 1) * 8;
    const uint32_t b_koff = ((lane >> 3) & 1) * 16;

    load_stage(sb, 0, row0, e, n0, 0);
    CP_COMMIT();
    load_stage(sb, 1, row0, e, n0, KC);
    CP_COMMIT();
    load_stage(sb, 2, row0, e, n0, 2 * KC);
    CP_COMMIT();

    int s = 0;
    for (int c = 0; c < NCHUNK; ++c) {
        CP_WAIT(2);
        __syncthreads();
        if (c + 3 < NCHUNK) load_stage(sb, (s + 3) % NSTAGE, row0, e, n0, (c + 3) * KC);
        CP_COMMIT();

        const uint32_t st = sb + s * STG;
        uint32_t a0[2][4], a1[2][4], w0[2][4], w1[2][4];
        #pragma unroll
        for (int mt = 0; mt < 2; ++mt) {
            const uint32_t ad = st + (a_row + mt * 16) * ROWB + a_koff;
            ldsm4(a0[mt], ad);               // X0 (k32 span)
            ldsm4(a1[mt], ad + BUFB);        // X1
        }
        #pragma unroll
        for (int nt2 = 0; nt2 < 2; ++nt2) {
            const uint32_t bd = st + 2 * BUFB + (b_row + nt2 * 16) * ROWB + b_koff;
            ldsm4(w0[nt2], bd);              // W0
            ldsm4(w1[nt2], bd + BUFB);       // W1
        }
        #pragma unroll
        for (int mt = 0; mt < 2; ++mt)
            #pragma unroll
            for (int nt = 0; nt < 4; ++nt) {
                const uint32_t* p0 = &w0[nt >> 1][(nt & 1) * 2];
                const uint32_t* p1 = &w1[nt >> 1][(nt & 1) * 2];
                mma_s8(accA[mt][nt], a0[mt], p0[0], p0[1]);   // X0*W0 -> main
                mma_s8(accC[mt][nt], a0[mt], p1[0], p1[1]);   // X0*W1 -> corr
                mma_s8(accC[mt][nt], a1[mt], p0[0], p0[1]);   // X1*W0 -> corr
            }
        s = (s + 1) % NSTAGE;
    }

    // epilogue: y = (accA + accC/128) * invqx[row]*invqw[col] + bias
    const float inv128 = 1.f / 128.f;
    const int ncol = n0 + warp_n * 32 + (lane & 3) * 2;
    float2 bias[4], fw[4];
    #pragma unroll
    for (int nt = 0; nt < 4; ++nt) {
        bias[nt] = *(const float2*)(b + (size_t)e * D_OUT + ncol + nt * 8);
        fw[nt]   = *(const float2*)(g_invqw + (size_t)e * D_OUT + ncol + nt * 8);
    }

    #pragma unroll
    for (int mt = 0; mt < 2; ++mt)
        #pragma unroll
        for (int half = 0; half < 2; ++half) {
            const int sr = row0 + warp_m * 32 + mt * 16 + (lane >> 2) + half * 8;
            if (sr < row_end) {
                const int g = g_perm[sr];
                const float fx = g_invqx[sr];
                float* yp = y + (size_t)g * D_OUT + ncol;
                #pragma unroll
                for (int nt = 0; nt < 4; ++nt) {
                    float v0 = (float)accA[mt][nt][half * 2 + 0]
                             + (float)accC[mt][nt][half * 2 + 0] * inv128;
                    float v1 = (float)accA[mt][nt][half * 2 + 1]
                             + (float)accC[mt][nt][half * 2 + 1] * inv128;
                    float2 v;
                    v.x = v0 * fx * fw[nt].x + bias[nt].x;
                    v.y = v1 * fx * fw[nt].y + bias[nt].y;
                    *(float2*)(yp + nt * 8) = v;
                }
            }
        }
}

// ---------------- entry -----------------------------------------------------
extern "C" void kernel_launch(void* const* d_in, const int* in_sizes, int n_in,
                              void* d_out, int out_size) {
    const float* x   = (const float*)d_in[0];
    const int*   idx = (const int*)  d_in[1];
    const float* W   = (const float*)d_in[2];
    const float* b   = (const float*)d_in[3];
    float*       y   = (float*)d_out;

    cudaFuncSetAttribute(k_gemm, cudaFuncAttributeMaxDynamicSharedMemorySize, SMEM_TOTAL);

    k_zero<<<1, 32>>>();
    k_hist<<<(N_ROWS + 255) / 256, 256>>>(idx);
    k_scan<<<1, 1>>>();
    k_scatter<<<(N_ROWS + 255) / 256, 256>>>(idx);
    k_convert_x<<<N_ROWS, 256>>>(x);
    k_convert_w<<<N_EXP * D_OUT, 256>>>(W);

    dim3 grid(MAX_TILES, D_OUT / BN);
    k_gemm<<<grid, NTHREADS, SMEM_TOTAL>>>(b, y);
}

// round 11
// speedup vs baseline: 1.8229x; 1.1963x over previous
#include <cuda_runtime.h>
#include <cuda_bf16.h>
#include <cstdint>

// Problem constants
#define N_ROWS 16384
#define D_IN   1024
#define D_OUT  512
#define N_EXP  8
#define NPAD   (N_ROWS + N_EXP * 128)   // 17408: per-expert 128-padded row space

// GEMM tiling
#define BM 128
#define BN 128
#define KC 32                           // K elems per chunk = one k32 int8 MMA step
#define NCHUNK (D_IN / KC)              // 32
#define NSTAGE 4
#define NTHREADS 512
#define MAX_TILES (N_ROWS / BM + N_EXP) // 136

// SMEM stage: X0 | X1 | W0 | W1, each 128 rows x 32B = 4KB -> 16KB/stage
#define STG 16384
#define SMEM_TOTAL (NSTAGE * STG)       // 65536

// ---------------- device scratch ------------------------------------------
__device__ int g_cnt[N_EXP];
__device__ int g_cur[N_EXP];
__device__ int g_off[N_EXP + 1];        // padded starts (multiples of 128)
__device__ int g_end[N_EXP];            // real ends in padded space
__device__ int g_perm[NPAD];
__device__ int g_tile_e[MAX_TILES];
__device__ int g_tile_r[MAX_TILES];
// chunk-major, bank-swizzled quantized streams
__device__ uint8_t g_x0c[(size_t)NCHUNK * NPAD * 32];
__device__ uint8_t g_x1c[(size_t)NCHUNK * NPAD * 32];
__device__ uint8_t g_w0c[(size_t)N_EXP * NCHUNK * D_OUT * 32];
__device__ uint8_t g_w1c[(size_t)N_EXP * NCHUNK * D_OUT * 32];
__device__ float   g_invqx[NPAD];
__device__ float   g_invqw[N_EXP * D_OUT];

// ---------------- PTX helpers ----------------------------------------------
__device__ __forceinline__ uint32_t smem_u32(const void* p) {
    uint32_t a;
    asm("{ .reg .u64 t; cvta.to.shared.u64 t, %1; cvt.u32.u64 %0, t; }" : "=r"(a) : "l"(p));
    return a;
}
#define MBARRIER_INIT(a, n) \
    asm volatile("mbarrier.init.shared.b64 [%0], %1;" :: "r"((uint32_t)(a)), "r"((uint32_t)(n)) : "memory")
#define MBARRIER_EXPECT_TX(a, tx) \
    asm volatile("mbarrier.arrive.expect_tx.shared.b64 _, [%0], %1;" :: "r"((uint32_t)(a)), "r"((uint32_t)(tx)) : "memory")
#define MBARRIER_WAIT_PARITY(a, ph) do { \
    uint32_t _m = (uint32_t)(a); uint32_t _p = (uint32_t)(ph); uint32_t _d; \
    asm volatile("{ .reg .pred p; mbarrier.try_wait.parity.acquire.cta.shared::cta.b64 p, [%1], %2; selp.b32 %0, 1, 0, p; }" \
        : "=r"(_d) : "r"(_m), "r"(_p) : "memory"); \
    if (!_d) { \
        asm volatile("{ .reg .pred P1; WL_%=: mbarrier.try_wait.parity.acquire.cta.shared::cta.b64 P1, [%0], %1, 0x989680; @P1 bra.uni WD_%=; bra.uni WL_%=; WD_%=: }" \
            :: "r"(_m), "r"(_p) : "memory"); \
    } } while (0)
__device__ __forceinline__ void bulk_g2s(uint32_t dst, const void* src, uint32_t bytes, uint32_t mbar) {
    asm volatile("cp.async.bulk.shared::cluster.global.mbarrier::complete_tx::bytes [%0], [%1], %2, [%3];"
                 :: "r"(dst), "l"(src), "r"(bytes), "r"(mbar) : "memory");
}
__device__ __forceinline__ void ldsm4(uint32_t* r, uint32_t a) {
    asm volatile("ldmatrix.sync.aligned.m8n8.x4.shared.b16 {%0,%1,%2,%3}, [%4];"
                 : "=r"(r[0]), "=r"(r[1]), "=r"(r[2]), "=r"(r[3]) : "r"(a));
}
__device__ __forceinline__ void mma_s8(int* c, const uint32_t* a, uint32_t b0, uint32_t b1) {
    asm volatile("mma.sync.aligned.m16n8k32.row.col.s32.s8.s8.s32 "
                 "{%0,%1,%2,%3}, {%4,%5,%6,%7}, {%8,%9}, {%0,%1,%2,%3};"
                 : "+r"(c[0]), "+r"(c[1]), "+r"(c[2]), "+r"(c[3])
                 : "r"(a[0]), "r"(a[1]), "r"(a[2]), "r"(a[3]), "r"(b0), "r"(b1));
}

// ---------------- bucketing -------------------------------------------------
__global__ void k_zero() {
    int t = threadIdx.x;
    if (t < N_EXP) { g_cnt[t] = 0; g_cur[t] = 0; }
}
__global__ void k_hist(const int* __restrict__ idx) {
    int i = blockIdx.x * blockDim.x + threadIdx.x;
    if (i < N_ROWS) atomicAdd(&g_cnt[idx[i]], 1);
}
__global__ void k_scan() {
    int off = 0, t = 0;
    for (int e = 0; e < N_EXP; ++e) {
        g_off[e] = off;
        int c = g_cnt[e];
        for (int r = 0; r < c; r += BM) { g_tile_e[t] = e; g_tile_r[t] = off + r; ++t; }
        g_end[e] = off + c;
        off += (c + BM - 1) & ~(BM - 1);      // pad to 128 multiple
    }
    g_off[N_EXP] = off;
    for (; t < MAX_TILES; ++t) g_tile_e[t] = -1;
}
__global__ void k_scatter(const int* __restrict__ idx) {
    int i = blockIdx.x * blockDim.x + threadIdx.x;
    if (i < N_ROWS) {
        int e = idx[i];
        g_perm[g_off[e] + atomicAdd(&g_cur[e], 1)] = i;
    }
}

// ---------------- int8 two-stream quantization (chunk-major, swizzled) ------
__device__ __forceinline__ float rowmax256(float4 v) {
    __shared__ float red[8];
    const int t = threadIdx.x;
    float m = fmaxf(fmaxf(fabsf(v.x), fabsf(v.y)), fmaxf(fabsf(v.z), fabsf(v.w)));
    #pragma unroll
    for (int o = 16; o > 0; o >>= 1) m = fmaxf(m, __shfl_xor_sync(0xffffffffu, m, o));
    if ((t & 31) == 0) red[t >> 5] = m;
    __syncthreads();
    if (t < 32) {
        float mm = (t < 8) ? red[t] : 0.f;
        #pragma unroll
        for (int o = 4; o > 0; o >>= 1) mm = fmaxf(mm, __shfl_xor_sync(0xffffffffu, mm, o));
        if (t == 0) red[0] = fmaxf(mm, 1e-30f);
    }
    __syncthreads();
    return red[0];
}
__device__ __forceinline__ void quant4(float4 v, float q, uchar4& c0, uchar4& c1) {
    uint8_t* p0 = (uint8_t*)&c0; uint8_t* p1 = (uint8_t*)&c1;
    float f[4] = {v.x, v.y, v.z, v.w};
    #pragma unroll
    for (int i = 0; i < 4; ++i) {
        float fq = f[i] * q;
        float x0 = rintf(fq);
        x0 = fminf(127.f, fmaxf(-127.f, x0));
        float x1 = rintf((fq - x0) * 128.f);
        x1 = fminf(127.f, fmaxf(-127.f, x1));
        p0[i] = (uint8_t)(int8_t)(int)x0;
        p1[i] = (uint8_t)(int8_t)(int)x1;
    }
}
__global__ void k_convert_x(const float* __restrict__ x) {
    const int p = blockIdx.x;                 // padded permuted row (stale perm ok)
    const int src = g_perm[p];
    const int t = threadIdx.x;                // 256 threads x 4 floats
    float4 v = ((const float4*)(x + (size_t)src * D_IN))[t];
    const float maxv = rowmax256(v);
    uchar4 c0, c1;
    quant4(v, 127.f / maxv, c0, c1);
    const int ck = t >> 3;
    const int j  = (t & 7) * 4;
    const int js = j ^ ((p & 4) ? 16 : 0);
    const size_t base = ((size_t)ck * NPAD + p) * 32 + js;
    *(uchar4*)(g_x0c + base) = c0;
    *(uchar4*)(g_x1c + base) = c1;
    if (t == 0) g_invqx[p] = maxv * (1.f / 127.f);
}
__global__ void k_convert_w(const float* __restrict__ W) {
    const int r = blockIdx.x;                 // 0..E*D_OUT-1
    const int e = r >> 9, co = r & 511;
    const int t = threadIdx.x;
    float4 v = ((const float4*)(W + (size_t)r * D_IN))[t];
    const float maxv = rowmax256(v);
    uchar4 c0, c1;
    quant4(v, 127.f / maxv, c0, c1);
    const int ck = t >> 3;
    const int j  = (t & 7) * 4;
    const int js = j ^ ((co & 4) ? 16 : 0);
    const size_t base = ((size_t)(e * NCHUNK + ck) * D_OUT + co) * 32 + js;
    *(uchar4*)(g_w0c + base) = c0;
    *(uchar4*)(g_w1c + base) = c1;
    if (t == 0) g_invqw[r] = maxv * (1.f / 127.f);
}

// ---------------- grouped int8 GEMM (bulk-copy pipeline) --------------------
__global__ void __launch_bounds__(NTHREADS, 1) k_gemm(const float* __restrict__ b,
                                                      float* __restrict__ y) {
    const int e = g_tile_e[blockIdx.x];
    if (e < 0) return;
    const int row0    = g_tile_r[blockIdx.x];
    const int row_end = g_end[e];
    const int n0      = blockIdx.y * BN;

    extern __shared__ char smem[];
    __shared__ uint64_t mbar[NSTAGE];
    const uint32_t sb = smem_u32(smem);

    const int tid  = threadIdx.x;
    const int lane = tid & 31;
    const int warp = tid >> 5;
    const int warp_m = warp >> 2;       // 0..3 (32 rows each)
    const int warp_n = warp & 3;        // 0..3 (32 cols each)

    if (tid == 0) {
        #pragma unroll
        for (int s = 0; s < NSTAGE; ++s) MBARRIER_INIT(smem_u32(&mbar[s]), 1);
    }
    __syncthreads();

    // producer helper (tid 0)
    auto issue = [&](int s, int ck) {
        const uint32_t mb = smem_u32(&mbar[s]);
        MBARRIER_EXPECT_TX(mb, STG);
        const uint32_t st = sb + s * STG;
        bulk_g2s(st,         g_x0c + ((size_t)ck * NPAD + row0) * 32, 4096, mb);
        bulk_g2s(st + 4096,  g_x1c + ((size_t)ck * NPAD + row0) * 32, 4096, mb);
        bulk_g2s(st + 8192,  g_w0c + ((size_t)(e * NCHUNK + ck) * D_OUT + n0) * 32, 4096, mb);
        bulk_g2s(st + 12288, g_w1c + ((size_t)(e * NCHUNK + ck) * D_OUT + n0) * 32, 4096, mb);
    };
    if (tid == 0) {
        issue(0, 0);
        issue(1, 1);
        issue(2, 2);
    }

    int accA[2][4][4], accC[2][4][4];
    #pragma unroll
    for (int i = 0; i < 2; ++i)
        #pragma unroll
        for (int j = 0; j < 4; ++j)
            #pragma unroll
            for (int k = 0; k < 4; ++k) { accA[i][j][k] = 0; accC[i][j][k] = 0; }

    const uint32_t a_row  = warp_m * 32 + (lane & 15);
    const uint32_t a_koff = (lane >> 4) * 16;
    const uint32_t aswz   = (a_row & 4) ? 16u : 0u;
    const uint32_t b_row  = warp_n * 32 + (lane & 7) + ((lane >> 4) & 1) * 8;
    const uint32_t b_koff = ((lane >> 3) & 1) * 16;
    const uint32_t bswz   = (b_row & 4) ? 16u : 0u;

    for (int c = 0; c < NCHUNK; ++c) {
        const int s = c & (NSTAGE - 1);
        MBARRIER_WAIT_PARITY(smem_u32(&mbar[s]), (c >> 2) & 1);
        __syncthreads();                       // all reads of stage (c-1) done
        if (tid == 0 && c + 3 < NCHUNK) issue((c + 3) & (NSTAGE - 1), c + 3);

        const uint32_t st = sb + s * STG;
        uint32_t a0[2][4], a1[2][4], w0[2][4], w1[2][4];
        #pragma unroll
        for (int mt = 0; mt < 2; ++mt) {
            const uint32_t ad = st + (a_row + mt * 16) * 32 + (a_koff ^ aswz);
            ldsm4(a0[mt], ad);
            ldsm4(a1[mt], ad + 4096);
        }
        #pragma unroll
        for (int nt2 = 0; nt2 < 2; ++nt2) {
            const uint32_t bd = st + 8192 + (b_row + nt2 * 16) * 32 + (b_koff ^ bswz);
            ldsm4(w0[nt2], bd);
            ldsm4(w1[nt2], bd + 4096);
        }
        #pragma unroll
        for (int mt = 0; mt < 2; ++mt)
            #pragma unroll
            for (int nt = 0; nt < 4; ++nt) {
                const uint32_t* p0 = &w0[nt >> 1][(nt & 1) * 2];
                const uint32_t* p1 = &w1[nt >> 1][(nt & 1) * 2];
                mma_s8(accA[mt][nt], a0[mt], p0[0], p0[1]);   // X0*W0 -> main
                mma_s8(accC[mt][nt], a0[mt], p1[0], p1[1]);   // X0*W1 -> corr
                mma_s8(accC[mt][nt], a1[mt], p0[0], p0[1]);   // X1*W0 -> corr
            }
    }

    // epilogue: y = (accA + accC/128) * invqx[row]*invqw[col] + bias
    const float inv128 = 1.f / 128.f;
    const int ncol = n0 + warp_n * 32 + (lane & 3) * 2;
    float2 bias[4], fw[4];
    #pragma unroll
    for (int nt = 0; nt < 4; ++nt) {
        bias[nt] = *(const float2*)(b + (size_t)e * D_OUT + ncol + nt * 8);
        fw[nt]   = *(const float2*)(g_invqw + (size_t)e * D_OUT + ncol + nt * 8);
    }
    #pragma unroll
    for (int mt = 0; mt < 2; ++mt)
        #pragma unroll
        for (int half = 0; half < 2; ++half) {
            const int sr = row0 + warp_m * 32 + mt * 16 + (lane >> 2) + half * 8;
            if (sr < row_end) {
                const int g = g_perm[sr];
                const float fx = g_invqx[sr];
                float* yp = y + (size_t)g * D_OUT + ncol;
                #pragma unroll
                for (int nt = 0; nt < 4; ++nt) {
                    float v0 = (float)accA[mt][nt][half * 2 + 0]
                             + (float)accC[mt][nt][half * 2 + 0] * inv128;
                    float v1 = (float)accA[mt][nt][half * 2 + 1]
                             + (float)accC[mt][nt][half * 2 + 1] * inv128;
                    float2 v;
                    v.x = v0 * fx * fw[nt].x + bias[nt].x;
                    v.y = v1 * fx * fw[nt].y + bias[nt].y;
                    *(float2*)(yp + nt * 8) = v;
                }
            }
        }
}

// ---------------- entry -----------------------------------------------------
extern "C" void kernel_launch(void* const* d_in, const int* in_sizes, int n_in,
                              void* d_out, int out_size) {
    const float* x   = (const float*)d_in[0];
    const int*   idx = (const int*)  d_in[1];
    const float* W   = (const float*)d_in[2];
    const float* b   = (const float*)d_in[3];
    float*       y   = (float*)d_out;

    cudaFuncSetAttribute(k_gemm, cudaFuncAttributeMaxDynamicSharedMemorySize, SMEM_TOTAL);

    k_zero<<<1, 32>>>();
    k_hist<<<(N_ROWS + 255) / 256, 256>>>(idx);
    k_scan<<<1, 1>>>();
    k_scatter<<<(N_ROWS + 255) / 256, 256>>>(idx);
    k_convert_x<<<NPAD, 256>>>(x);
    k_convert_w<<<N_EXP * D_OUT, 256>>>(W);

    dim3 grid(MAX_TILES, D_OUT / BN);
    k_gemm<<<grid, NTHREADS, SMEM_TOTAL>>>(b, y);
}